// round 1
// baseline (speedup 1.0000x reference)
#include <cuda_runtime.h>
#include <cstdint>

#define TM 256
#define THREADS 256

typedef unsigned long long ull;

__device__ __forceinline__ ull pack2(float lo, float hi) {
    ull r; asm("mov.b64 %0, {%1, %2};" : "=l"(r) : "f"(lo), "f"(hi)); return r;
}
__device__ __forceinline__ void unpack2(ull v, float &lo, float &hi) {
    asm("mov.b64 {%0, %1}, %2;" : "=f"(lo), "=f"(hi) : "l"(v));
}
__device__ __forceinline__ void fma2(ull &d, ull a, ull b) {
    asm("fma.rn.f32x2 %0, %1, %2, %3;" : "=l"(d) : "l"(a), "l"(b), "l"(d));
}

// SMEM layout (floats):
//   W1s : 192*64      = 12288
//   W2s : 64*64       = 4096
//   b1s : 64
//   b2s : 64
//   Xs  : 256*65      = 16640   (stride-65 pad; reused as Hs for GEMM2)
// total = 33152 floats = 132608 bytes
#define SMEM_FLOATS 33152
#define SMEM_BYTES  (SMEM_FLOATS * 4)

__global__ __launch_bounds__(THREADS, 1)
void edge_mlp_kernel(const float* __restrict__ src, const float* __restrict__ dst,
                     const float* __restrict__ ea,
                     const float* __restrict__ W1, const float* __restrict__ b1,
                     const float* __restrict__ W2, const float* __restrict__ b2,
                     float* __restrict__ out, int E)
{
    extern __shared__ float smem[];
    float* W1s = smem;                 // 12288
    float* W2s = W1s + 192 * 64;       // 4096
    float* b1s = W2s + 64 * 64;        // 64
    float* b2s = b1s + 64;             // 64
    float* Xs  = b2s + 64;             // 256*65

    const int tid = threadIdx.x;
    const int e0  = blockIdx.x * TM;

    // ---- cooperative weight/bias staging (coalesced float4) ----
    {
        const float4* g1 = (const float4*)W1;
        float4* s1 = (float4*)W1s;
        #pragma unroll
        for (int i = 0; i < 12; ++i) s1[tid + i * THREADS] = g1[tid + i * THREADS];
        const float4* g2 = (const float4*)W2;
        float4* s2 = (float4*)W2s;
        #pragma unroll
        for (int i = 0; i < 4; ++i) s2[tid + i * THREADS] = g2[tid + i * THREADS];
        if (tid < 64) { b1s[tid] = b1[tid]; b2s[tid] = b2[tid]; }
    }

    // micro-tile mapping: 8 rows x 8 cols per thread
    const int tx = tid & 7;          // col group -> cols 8*tx .. 8*tx+7
    const int ty = tid >> 3;         // row group -> rows 8*ty .. 8*ty+7
    const int m0 = ty * 8;
    const int c0 = tx * 8;

    ull acc[8][4];                   // 8 rows x 4 f32x2 pairs (8 cols)
    #pragma unroll
    for (int i = 0; i < 8; ++i)
        #pragma unroll
        for (int j = 0; j < 4; ++j) acc[i][j] = 0ULL;   // (0.0f, 0.0f)

    // ================= GEMM1: K = 3 segments of 64 =================
    for (int seg = 0; seg < 3; ++seg) {
        const float* __restrict__ p = (seg == 0) ? src : (seg == 1) ? dst : ea;
        __syncthreads();   // protect Xs reuse across segments (and order weight stage before use)
        // stage X tile: 256 rows x 64 cols, fully coalesced global float4 reads
        #pragma unroll
        for (int t = 0; t < 16; ++t) {
            int idx = tid + t * THREADS;
            int kq  = idx & 15;       // which float4 within the row
            int m   = idx >> 4;       // row within tile
            int e   = e0 + m;
            float4 v;
            if (e < E) v = ((const float4*)p)[(size_t)e * 16 + kq];
            else       v = make_float4(0.f, 0.f, 0.f, 0.f);
            float* xr = &Xs[m * 65 + kq * 4];
            xr[0] = v.x; xr[1] = v.y; xr[2] = v.z; xr[3] = v.w;
        }
        __syncthreads();

        const float* wseg = &W1s[seg * 64 * 64];
        #pragma unroll 4
        for (int kk = 0; kk < 64; ++kk) {
            // b: 8 weight floats for this k row (16B-aligned vector loads)
            ulonglong2 w01 = *(const ulonglong2*)&wseg[kk * 64 + c0];
            ulonglong2 w23 = *(const ulonglong2*)&wseg[kk * 64 + c0 + 4];
            #pragma unroll
            for (int i = 0; i < 8; ++i) {
                float av = Xs[(m0 + i) * 65 + kk];   // broadcast (4 distinct addrs/warp)
                ull a2 = pack2(av, av);
                fma2(acc[i][0], a2, w01.x);
                fma2(acc[i][1], a2, w01.y);
                fma2(acc[i][2], a2, w23.x);
                fma2(acc[i][3], a2, w23.y);
            }
        }
    }

    __syncthreads();
    // ---- bias1 + ReLU -> Hs (reuse Xs), reset accumulators ----
    #pragma unroll
    for (int i = 0; i < 8; ++i) {
        float* hr = &Xs[(m0 + i) * 65 + c0];
        #pragma unroll
        for (int j = 0; j < 4; ++j) {
            float lo, hi; unpack2(acc[i][j], lo, hi);
            lo += b1s[c0 + 2 * j];
            hi += b1s[c0 + 2 * j + 1];
            hr[2 * j]     = fmaxf(lo, 0.f);
            hr[2 * j + 1] = fmaxf(hi, 0.f);
            acc[i][j] = 0ULL;
        }
    }
    __syncthreads();

    // ================= GEMM2: K = 64 =================
    #pragma unroll 4
    for (int kk = 0; kk < 64; ++kk) {
        ulonglong2 w01 = *(const ulonglong2*)&W2s[kk * 64 + c0];
        ulonglong2 w23 = *(const ulonglong2*)&W2s[kk * 64 + c0 + 4];
        #pragma unroll
        for (int i = 0; i < 8; ++i) {
            float av = Xs[(m0 + i) * 65 + kk];
            ull a2 = pack2(av, av);
            fma2(acc[i][0], a2, w01.x);
            fma2(acc[i][1], a2, w01.y);
            fma2(acc[i][2], a2, w23.x);
            fma2(acc[i][3], a2, w23.y);
        }
    }

    // ---- epilogue: + bias2, coalesced float4 stores ----
    #pragma unroll
    for (int i = 0; i < 8; ++i) {
        int e = e0 + m0 + i;
        if (e < E) {
            float v0, v1, v2, v3, v4, v5, v6, v7;
            unpack2(acc[i][0], v0, v1);
            unpack2(acc[i][1], v2, v3);
            unpack2(acc[i][2], v4, v5);
            unpack2(acc[i][3], v6, v7);
            float4 o0 = make_float4(v0 + b2s[c0],     v1 + b2s[c0 + 1],
                                    v2 + b2s[c0 + 2], v3 + b2s[c0 + 3]);
            float4 o1 = make_float4(v4 + b2s[c0 + 4], v5 + b2s[c0 + 5],
                                    v6 + b2s[c0 + 6], v7 + b2s[c0 + 7]);
            float4* op = (float4*)&out[(size_t)e * 64 + c0];
            op[0] = o0;
            op[1] = o1;
        }
    }
}

extern "C" void kernel_launch(void* const* d_in, const int* in_sizes, int n_in,
                              void* d_out, int out_size)
{
    // metadata order: 0=src 1=dest 2=edge_attr 3=u(unused) 4=batch(unused,int64)
    //                 5=W1[192,64] 6=bias1[64] 7=W2[64,64] 8=bias2[64]
    const float* src = (const float*)d_in[0];
    const float* dst = (const float*)d_in[1];
    const float* ea  = (const float*)d_in[2];
    const float* W1  = (const float*)d_in[5];
    const float* b1  = (const float*)d_in[6];
    const float* W2  = (const float*)d_in[7];
    const float* b2  = (const float*)d_in[8];
    float* out = (float*)d_out;

    int E = in_sizes[0] / 64;

    cudaFuncSetAttribute(edge_mlp_kernel,
                         cudaFuncAttributeMaxDynamicSharedMemorySize, SMEM_BYTES);

    int grid = (E + TM - 1) / TM;
    edge_mlp_kernel<<<grid, THREADS, SMEM_BYTES>>>(src, dst, ea, W1, b1, W2, b2, out, E);
}

// round 3
// speedup vs baseline: 1.9966x; 1.9966x over previous
#include <cuda_runtime.h>
#include <cstdint>

#define THREADS 256
#define M_TILE  128

// ---------------- SMEM layout (bytes) ----------------
// [256]  b1 (64 f32)   [512] b2 (64 f32)
// OFF_X : 6 buffers of 16384B = [128 rows x 64 bf16] (seg0hi, seg0lo, seg1hi, seg1lo, seg2hi, seg2lo)
//         buffers 0/1 are reused as H hi/lo for GEMM2
// OFF_W1: hi, lo  [192 rows x 64 bf16] = 24576 each   (row-major [k][n])
// OFF_W2: hi, lo  [64  rows x 64 bf16] = 8192  each
#define OFF_B1 256
#define OFF_B2 512
#define OFF_X  1024
#define XBUF(i)  (OFF_X + (i) * 16384)
#define OFF_W1 (OFF_X + 6 * 16384)
#define OFF_W2 (OFF_W1 + 2 * 24576)
#define SMEM_BYTES (OFF_W2 + 2 * 8192)   // 164864

// ---------------- helpers ----------------
__device__ __forceinline__ uint32_t smem_u32(const void* p) {
    uint32_t a;
    asm("{ .reg .u64 t; cvta.to.shared.u64 t, %1; cvt.u32.u64 %0, t; }" : "=r"(a) : "l"(p));
    return a;
}
__device__ __forceinline__ uint32_t sw128(uint32_t o) { return o ^ ((o >> 3) & 0x70); }

// pack: e0 -> low half, e1 -> high half
__device__ __forceinline__ uint32_t pack2bf(float e0, float e1) {
    uint32_t r;
    asm("cvt.rn.bf16x2.f32 %0, %1, %2;" : "=r"(r) : "f"(e1), "f"(e0));
    return r;
}

// split 4 fp32 into bf16 hi/lo, 8B store each
__device__ __forceinline__ void split_store(char* hip, char* lop, float4 v) {
    uint32_t h01 = pack2bf(v.x, v.y);
    uint32_t h23 = pack2bf(v.z, v.w);
    float f0 = __uint_as_float(h01 << 16);
    float f1 = __uint_as_float(h01 & 0xFFFF0000u);
    float f2 = __uint_as_float(h23 << 16);
    float f3 = __uint_as_float(h23 & 0xFFFF0000u);
    uint32_t l01 = pack2bf(v.x - f0, v.y - f1);
    uint32_t l23 = pack2bf(v.z - f2, v.w - f3);
    *reinterpret_cast<uint2*>(hip) = make_uint2(h01, h23);
    *reinterpret_cast<uint2*>(lop) = make_uint2(l01, l23);
}

__device__ __forceinline__ void ldsm4(uint32_t r[4], uint32_t addr) {
    asm volatile("ldmatrix.sync.aligned.m8n8.x4.shared.b16 {%0,%1,%2,%3}, [%4];"
        : "=r"(r[0]), "=r"(r[1]), "=r"(r[2]), "=r"(r[3]) : "r"(addr));
}
__device__ __forceinline__ void ldsm4t(uint32_t r[4], uint32_t addr) {
    asm volatile("ldmatrix.sync.aligned.m8n8.x4.trans.shared.b16 {%0,%1,%2,%3}, [%4];"
        : "=r"(r[0]), "=r"(r[1]), "=r"(r[2]), "=r"(r[3]) : "r"(addr));
}
__device__ __forceinline__ void mma16816(float c[4], const uint32_t a[4], const uint32_t b[2]) {
    asm volatile(
        "mma.sync.aligned.m16n8k16.row.col.f32.bf16.bf16.f32 "
        "{%0,%1,%2,%3}, {%4,%5,%6,%7}, {%8,%9}, {%0,%1,%2,%3};"
        : "+f"(c[0]), "+f"(c[1]), "+f"(c[2]), "+f"(c[3])
        : "r"(a[0]), "r"(a[1]), "r"(a[2]), "r"(a[3]), "r"(b[0]), "r"(b[1]));
}

// ldmatrix tile address: 16x16 region at (rbase, cbase-in-elements) of a
// [rows x 64 bf16] swizzled buffer; lane supplies one 16B row of one 8x8 tile.
__device__ __forceinline__ uint32_t frag_addr(uint32_t base, int rbase, int cbase, int lane) {
    int row  = rbase + (lane & 15);
    int colb = cbase * 2 + (lane & 16);
    return base + sw128((uint32_t)(row * 128 + colb));
}

__global__ __launch_bounds__(THREADS, 1)
void edge_mlp_mma(const float* __restrict__ src, const float* __restrict__ dst,
                  const float* __restrict__ ea,
                  const float* __restrict__ W1, const float* __restrict__ b1,
                  const float* __restrict__ W2, const float* __restrict__ b2,
                  float* __restrict__ out, int E)
{
    extern __shared__ char smem[];
    const uint32_t sb = smem_u32(smem);
    const int tid = threadIdx.x;
    const int wid = tid >> 5;
    const int lid = tid & 31;
    const int e0  = blockIdx.x * M_TILE;

    const int wm = wid & 3;   // M group: rows 32*wm .. +31
    const int wn = wid >> 2;  // N group: cols 32*wn .. +31

    // ---- biases ----
    if (tid < 64) {
        ((float*)(smem + OFF_B1))[tid] = b1[tid];
        ((float*)(smem + OFF_B2))[tid] = b2[tid];
    }

    // ---- stage W1 hi/lo ([192 x 64 bf16], swizzled 128B rows) ----
    #pragma unroll
    for (int i = 0; i < 12; ++i) {
        int idx = tid + i * THREADS;               // float4 index, 0..3071
        int k = idx >> 4;
        uint32_t off = sw128((uint32_t)(k * 128 + (idx & 15) * 8));
        float4 v = ((const float4*)W1)[idx];
        split_store(smem + OFF_W1 + off, smem + OFF_W1 + 24576 + off, v);
    }
    // ---- stage W2 hi/lo ----
    #pragma unroll
    for (int i = 0; i < 4; ++i) {
        int idx = tid + i * THREADS;               // 0..1023
        int k = idx >> 4;
        uint32_t off = sw128((uint32_t)(k * 128 + (idx & 15) * 8));
        float4 v = ((const float4*)W2)[idx];
        split_store(smem + OFF_W2 + off, smem + OFF_W2 + 8192 + off, v);
    }

    // ---- X segment staging (register prefetch + split store) ----
    float4 pre[8];
    auto load_regs = [&](const float* __restrict__ p) {
        #pragma unroll
        for (int i = 0; i < 8; ++i) {
            int idx = tid + i * THREADS;           // 0..2047
            int m = idx >> 4;
            int e = e0 + m;
            pre[i] = (e < E) ? ((const float4*)p)[(size_t)e * 16 + (idx & 15)]
                             : make_float4(0.f, 0.f, 0.f, 0.f);
        }
    };
    auto store_seg = [&](int s) {
        char* hib = smem + XBUF(2 * s);
        char* lob = smem + XBUF(2 * s + 1);
        #pragma unroll
        for (int i = 0; i < 8; ++i) {
            int idx = tid + i * THREADS;
            int m = idx >> 4;
            uint32_t off = sw128((uint32_t)(m * 128 + (idx & 15) * 8));
            split_store(hib + off, lob + off, pre[i]);
        }
    };

    float acc[2][4][4];
    #pragma unroll
    for (int mt = 0; mt < 2; ++mt)
        #pragma unroll
        for (int nt = 0; nt < 4; ++nt)
            #pragma unroll
            for (int j = 0; j < 4; ++j) acc[mt][nt][j] = 0.f;

    // one k-step (16 k) of GEMM: A from (ahib, alob) at kk, B from (bhib, blob) at kglob
    auto kstep = [&](uint32_t ahib, uint32_t alob, int kk,
                     uint32_t bhib, uint32_t blob, int kg) {
        uint32_t ahi[2][4], alo[2][4], bhi[2][4], blo[2][4];
        ldsm4(ahi[0], frag_addr(ahib, wm * 32,      kk, lid));
        ldsm4(ahi[1], frag_addr(ahib, wm * 32 + 16, kk, lid));
        ldsm4(alo[0], frag_addr(alob, wm * 32,      kk, lid));
        ldsm4(alo[1], frag_addr(alob, wm * 32 + 16, kk, lid));
        ldsm4t(bhi[0], frag_addr(bhib, kg, wn * 32,      lid));
        ldsm4t(bhi[1], frag_addr(bhib, kg, wn * 32 + 16, lid));
        ldsm4t(blo[0], frag_addr(blob, kg, wn * 32,      lid));
        ldsm4t(blo[1], frag_addr(blob, kg, wn * 32 + 16, lid));
        #pragma unroll
        for (int mt = 0; mt < 2; ++mt)
            #pragma unroll
            for (int nt = 0; nt < 4; ++nt) {
                const uint32_t* bh = &bhi[nt >> 1][(nt & 1) * 2];
                const uint32_t* bl = &blo[nt >> 1][(nt & 1) * 2];
                mma16816(acc[mt][nt], ahi[mt], bh);
                mma16816(acc[mt][nt], ahi[mt], bl);
                mma16816(acc[mt][nt], alo[mt], bh);
            }
    };

    // ================= GEMM1 (K = 192, 12 k-steps, 3 segments) =================
    load_regs(src);
    store_seg(0);
    __syncthreads();
    load_regs(dst);                                   // prefetch seg1 during seg0 mma
    #pragma unroll
    for (int ks = 0; ks < 4; ++ks)
        kstep(sb + XBUF(0), sb + XBUF(1), ks * 16,
              sb + OFF_W1, sb + OFF_W1 + 24576, ks * 16);
    store_seg(1);
    __syncthreads();
    load_regs(ea);                                    // prefetch seg2 during seg1 mma
    #pragma unroll
    for (int ks = 0; ks < 4; ++ks)
        kstep(sb + XBUF(2), sb + XBUF(3), ks * 16,
              sb + OFF_W1, sb + OFF_W1 + 24576, 64 + ks * 16);
    store_seg(2);
    __syncthreads();
    #pragma unroll
    for (int ks = 0; ks < 4; ++ks)
        kstep(sb + XBUF(4), sb + XBUF(5), ks * 16,
              sb + OFF_W1, sb + OFF_W1 + 24576, 128 + ks * 16);

    __syncthreads();   // all GEMM1 reads done before H overwrites XBUF(0,1)

    // ---- bias1 + ReLU + split -> H (XBUF 0 = hi, XBUF 1 = lo) ----
    {
        const float* b1s = (const float*)(smem + OFF_B1);
        #pragma unroll
        for (int mt = 0; mt < 2; ++mt)
            #pragma unroll
            for (int nt = 0; nt < 4; ++nt) {
                int row = wm * 32 + mt * 16 + (lid >> 2);
                int col = wn * 32 + nt * 8 + (lid & 3) * 2;
                float bc0 = b1s[col], bc1 = b1s[col + 1];
                // c0,c1 -> (row, col/col+1) ; c2,c3 -> (row+8, ...)
                float h0 = fmaxf(acc[mt][nt][0] + bc0, 0.f);
                float h1 = fmaxf(acc[mt][nt][1] + bc1, 0.f);
                float h2 = fmaxf(acc[mt][nt][2] + bc0, 0.f);
                float h3 = fmaxf(acc[mt][nt][3] + bc1, 0.f);
                uint32_t hA = pack2bf(h0, h1);
                uint32_t hB = pack2bf(h2, h3);
                uint32_t lA = pack2bf(h0 - __uint_as_float(hA << 16),
                                      h1 - __uint_as_float(hA & 0xFFFF0000u));
                uint32_t lB = pack2bf(h2 - __uint_as_float(hB << 16),
                                      h3 - __uint_as_float(hB & 0xFFFF0000u));
                uint32_t oA = sw128((uint32_t)(row * 128 + col * 2));
                uint32_t oB = sw128((uint32_t)((row + 8) * 128 + col * 2));
                *(uint32_t*)(smem + XBUF(0) + oA) = hA;
                *(uint32_t*)(smem + XBUF(1) + oA) = lA;
                *(uint32_t*)(smem + XBUF(0) + oB) = hB;
                *(uint32_t*)(smem + XBUF(1) + oB) = lB;
                // reset accumulators for GEMM2
                acc[mt][nt][0] = acc[mt][nt][1] = acc[mt][nt][2] = acc[mt][nt][3] = 0.f;
            }
    }
    __syncthreads();

    // ================= GEMM2 (K = 64) =================
    #pragma unroll
    for (int ks = 0; ks < 4; ++ks)
        kstep(sb + XBUF(0), sb + XBUF(1), ks * 16,
              sb + OFF_W2, sb + OFF_W2 + 8192, ks * 16);

    // ---- epilogue: + bias2, float2 stores ----
    {
        const float* b2s = (const float*)(smem + OFF_B2);
        #pragma unroll
        for (int mt = 0; mt < 2; ++mt)
            #pragma unroll
            for (int nt = 0; nt < 4; ++nt) {
                int row = wm * 32 + mt * 16 + (lid >> 2);
                int col = wn * 32 + nt * 8 + (lid & 3) * 2;
                float bc0 = b2s[col], bc1 = b2s[col + 1];
                int eA = e0 + row, eB = e0 + row + 8;
                if (eA < E)
                    *(float2*)&out[(size_t)eA * 64 + col] =
                        make_float2(acc[mt][nt][0] + bc0, acc[mt][nt][1] + bc1);
                if (eB < E)
                    *(float2*)&out[(size_t)eB * 64 + col] =
                        make_float2(acc[mt][nt][2] + bc0, acc[mt][nt][3] + bc1);
            }
    }
}

extern "C" void kernel_launch(void* const* d_in, const int* in_sizes, int n_in,
                              void* d_out, int out_size)
{
    const float* src = (const float*)d_in[0];
    const float* dst = (const float*)d_in[1];
    const float* ea  = (const float*)d_in[2];
    const float* W1  = (const float*)d_in[5];
    const float* b1  = (const float*)d_in[6];
    const float* W2  = (const float*)d_in[7];
    const float* b2  = (const float*)d_in[8];
    float* out = (float*)d_out;

    int E = in_sizes[0] / 64;

    cudaFuncSetAttribute(edge_mlp_mma,
                         cudaFuncAttributeMaxDynamicSharedMemorySize, SMEM_BYTES);

    int grid = (E + M_TILE - 1) / M_TILE;
    edge_mlp_mma<<<grid, THREADS, SMEM_BYTES>>>(src, dst, ea, W1, b1, W2, b2, out, E);
}

// round 4
// speedup vs baseline: 2.6436x; 1.3241x over previous
#include <cuda_runtime.h>
#include <cstdint>

#define THREADS 256
#define M_TILE  128

// ---------------- SMEM layout (bytes), all MMA buffers 1024-aligned ----------------
#define OFF_B1   0
#define OFF_B2   256
#define OFF_XHI  1024
#define OFF_XLO  (OFF_XHI + 16384)     // 17408
#define OFF_W1HI (OFF_XLO + 16384)     // 33792
#define OFF_W1LO (OFF_W1HI + 24576)    // 58368
#define OFF_W2HI (OFF_W1LO + 24576)    // 82944
#define OFF_W2LO (OFF_W2HI + 8192)     // 91136
#define SMEM_BYTES (OFF_W2LO + 8192)   // 99328  -> 2 CTAs/SM

// ---------------- helpers ----------------
__device__ __forceinline__ uint32_t smem_u32(const void* p) {
    uint32_t a;
    asm("{ .reg .u64 t; cvta.to.shared.u64 t, %1; cvt.u32.u64 %0, t; }" : "=r"(a) : "l"(p));
    return a;
}
__device__ __forceinline__ uint32_t sw128(uint32_t o) { return o ^ ((o >> 3) & 0x70); }

// pack: e0 -> low half, e1 -> high half
__device__ __forceinline__ uint32_t pack2bf(float e0, float e1) {
    uint32_t r;
    asm("cvt.rn.bf16x2.f32 %0, %1, %2;" : "=r"(r) : "f"(e1), "f"(e0));
    return r;
}

// split 4 fp32 into bf16 hi/lo, 8B store each
__device__ __forceinline__ void split_store(char* hip, char* lop, float4 v) {
    uint32_t h01 = pack2bf(v.x, v.y);
    uint32_t h23 = pack2bf(v.z, v.w);
    float f0 = __uint_as_float(h01 << 16);
    float f1 = __uint_as_float(h01 & 0xFFFF0000u);
    float f2 = __uint_as_float(h23 << 16);
    float f3 = __uint_as_float(h23 & 0xFFFF0000u);
    uint32_t l01 = pack2bf(v.x - f0, v.y - f1);
    uint32_t l23 = pack2bf(v.z - f2, v.w - f3);
    *reinterpret_cast<uint2*>(hip) = make_uint2(h01, h23);
    *reinterpret_cast<uint2*>(lop) = make_uint2(l01, l23);
}

__device__ __forceinline__ void ldsm4(uint32_t r[4], uint32_t addr) {
    asm volatile("ldmatrix.sync.aligned.m8n8.x4.shared.b16 {%0,%1,%2,%3}, [%4];"
        : "=r"(r[0]), "=r"(r[1]), "=r"(r[2]), "=r"(r[3]) : "r"(addr));
}
__device__ __forceinline__ void ldsm4t(uint32_t r[4], uint32_t addr) {
    asm volatile("ldmatrix.sync.aligned.m8n8.x4.trans.shared.b16 {%0,%1,%2,%3}, [%4];"
        : "=r"(r[0]), "=r"(r[1]), "=r"(r[2]), "=r"(r[3]) : "r"(addr));
}
__device__ __forceinline__ void mma16816(float c[4], const uint32_t a[4], const uint32_t b[2]) {
    asm volatile(
        "mma.sync.aligned.m16n8k16.row.col.f32.bf16.bf16.f32 "
        "{%0,%1,%2,%3}, {%4,%5,%6,%7}, {%8,%9}, {%0,%1,%2,%3};"
        : "+f"(c[0]), "+f"(c[1]), "+f"(c[2]), "+f"(c[3])
        : "r"(a[0]), "r"(a[1]), "r"(a[2]), "r"(a[3]), "r"(b[0]), "r"(b[1]));
}

// ldmatrix tile address: 16x16 region at (rbase, cbase-in-elements) of a
// [rows x 64 bf16] swizzled buffer; each lane supplies one 16B row of one 8x8 tile.
__device__ __forceinline__ uint32_t frag_addr(uint32_t base, int rbase, int cbase, int lane) {
    int row  = rbase + (lane & 15);
    int colb = cbase * 2 + (lane & 16);
    return base + sw128((uint32_t)(row * 128 + colb));
}

__global__ __launch_bounds__(THREADS, 2)
void edge_mlp_mma(const float* __restrict__ src, const float* __restrict__ dst,
                  const float* __restrict__ ea,
                  const float* __restrict__ W1, const float* __restrict__ b1,
                  const float* __restrict__ W2, const float* __restrict__ b2,
                  float* __restrict__ out, int E)
{
    extern __shared__ char smem[];
    const uint32_t sb = smem_u32(smem);
    const int tid = threadIdx.x;
    const int lid = tid & 31;
    const int wid = tid >> 5;
    const int e0  = blockIdx.x * M_TILE;

    const int wm = wid & 3;   // M group: rows 32*wm .. +31
    const int wn = wid >> 2;  // N group: cols 32*wn .. +31

    // ---- biases ----
    if (tid < 64) {
        ((float*)(smem + OFF_B1))[tid] = b1[tid];
        ((float*)(smem + OFF_B2))[tid] = b2[tid];
    }

    // ---- stage W1 / W2 hi+lo (swizzled 128B rows, row-major [k][n]) ----
    #pragma unroll
    for (int i = 0; i < 12; ++i) {
        int idx = tid + i * THREADS;               // float4 index, 0..3071
        uint32_t off = sw128((uint32_t)((idx >> 4) * 128 + (idx & 15) * 8));
        float4 v = ((const float4*)W1)[idx];
        split_store(smem + OFF_W1HI + off, smem + OFF_W1LO + off, v);
    }
    #pragma unroll
    for (int i = 0; i < 4; ++i) {
        int idx = tid + i * THREADS;               // 0..1023
        uint32_t off = sw128((uint32_t)((idx >> 4) * 128 + (idx & 15) * 8));
        float4 v = ((const float4*)W2)[idx];
        split_store(smem + OFF_W2HI + off, smem + OFF_W2LO + off, v);
    }

    // ---- X staging: direct GMEM -> split -> SMEM (latency hidden by co-resident CTA) ----
    auto stage_x = [&](const float* __restrict__ p) {
        #pragma unroll
        for (int i = 0; i < 8; ++i) {
            int idx = tid + i * THREADS;           // 0..2047
            int m = idx >> 4;
            int e = e0 + m;
            float4 v = (e < E) ? ((const float4*)p)[(size_t)e * 16 + (idx & 15)]
                               : make_float4(0.f, 0.f, 0.f, 0.f);
            uint32_t off = sw128((uint32_t)(m * 128 + (idx & 15) * 8));
            split_store(smem + OFF_XHI + off, smem + OFF_XLO + off, v);
        }
    };

    float acc[2][4][4];
    #pragma unroll
    for (int mt = 0; mt < 2; ++mt)
        #pragma unroll
        for (int nt = 0; nt < 4; ++nt)
            #pragma unroll
            for (int j = 0; j < 4; ++j) acc[mt][nt][j] = 0.f;

    // one 16-wide k-step: A from X hi/lo at col kk, B from weight buffers at row kg
    auto kstep = [&](int kk, uint32_t bhib, uint32_t blob, int kg) {
        uint32_t bhi[2][4], blo[2][4];
        ldsm4t(bhi[0], frag_addr(bhib, kg, wn * 32,      lid));
        ldsm4t(bhi[1], frag_addr(bhib, kg, wn * 32 + 16, lid));
        ldsm4t(blo[0], frag_addr(blob, kg, wn * 32,      lid));
        ldsm4t(blo[1], frag_addr(blob, kg, wn * 32 + 16, lid));
        #pragma unroll
        for (int mt = 0; mt < 2; ++mt) {
            uint32_t ahi[4], alo[4];
            ldsm4(ahi, frag_addr(sb + OFF_XHI, wm * 32 + mt * 16, kk, lid));
            ldsm4(alo, frag_addr(sb + OFF_XLO, wm * 32 + mt * 16, kk, lid));
            #pragma unroll
            for (int nt = 0; nt < 4; ++nt) {
                const uint32_t* bh = &bhi[nt >> 1][(nt & 1) * 2];
                const uint32_t* bl = &blo[nt >> 1][(nt & 1) * 2];
                mma16816(acc[mt][nt], ahi, bh);
                mma16816(acc[mt][nt], ahi, bl);
                mma16816(acc[mt][nt], alo, bh);
            }
        }
    };

    // ================= GEMM1 (K = 192, 3 segments through one X buffer) =================
    stage_x(src);
    __syncthreads();                               // X + weights ready
    #pragma unroll
    for (int ks = 0; ks < 4; ++ks)
        kstep(ks * 16, sb + OFF_W1HI, sb + OFF_W1LO, ks * 16);
    __syncthreads();                               // readers done

    stage_x(dst);
    __syncthreads();
    #pragma unroll
    for (int ks = 0; ks < 4; ++ks)
        kstep(ks * 16, sb + OFF_W1HI, sb + OFF_W1LO, 64 + ks * 16);
    __syncthreads();

    stage_x(ea);
    __syncthreads();
    #pragma unroll
    for (int ks = 0; ks < 4; ++ks)
        kstep(ks * 16, sb + OFF_W1HI, sb + OFF_W1LO, 128 + ks * 16);
    __syncthreads();                               // GEMM1 reads done; X free for H

    // ---- bias1 + ReLU + split -> H (reuse X hi/lo) ----
    {
        const float* b1s = (const float*)(smem + OFF_B1);
        #pragma unroll
        for (int mt = 0; mt < 2; ++mt)
            #pragma unroll
            for (int nt = 0; nt < 4; ++nt) {
                int row = wm * 32 + mt * 16 + (lid >> 2);
                int col = wn * 32 + nt * 8 + (lid & 3) * 2;
                float bc0 = b1s[col], bc1 = b1s[col + 1];
                float h0 = fmaxf(acc[mt][nt][0] + bc0, 0.f);
                float h1 = fmaxf(acc[mt][nt][1] + bc1, 0.f);
                float h2 = fmaxf(acc[mt][nt][2] + bc0, 0.f);
                float h3 = fmaxf(acc[mt][nt][3] + bc1, 0.f);
                uint32_t hA = pack2bf(h0, h1);
                uint32_t hB = pack2bf(h2, h3);
                uint32_t lA = pack2bf(h0 - __uint_as_float(hA << 16),
                                      h1 - __uint_as_float(hA & 0xFFFF0000u));
                uint32_t lB = pack2bf(h2 - __uint_as_float(hB << 16),
                                      h3 - __uint_as_float(hB & 0xFFFF0000u));
                uint32_t oA = sw128((uint32_t)(row * 128 + col * 2));
                uint32_t oB = sw128((uint32_t)((row + 8) * 128 + col * 2));
                *(uint32_t*)(smem + OFF_XHI + oA) = hA;
                *(uint32_t*)(smem + OFF_XLO + oA) = lA;
                *(uint32_t*)(smem + OFF_XHI + oB) = hB;
                *(uint32_t*)(smem + OFF_XLO + oB) = lB;
                acc[mt][nt][0] = acc[mt][nt][1] = acc[mt][nt][2] = acc[mt][nt][3] = 0.f;
            }
    }
    __syncthreads();

    // ================= GEMM2 (K = 64) =================
    #pragma unroll
    for (int ks = 0; ks < 4; ++ks)
        kstep(ks * 16, sb + OFF_W2HI, sb + OFF_W2LO, ks * 16);

    // ---- epilogue: + bias2, float2 stores ----
    {
        const float* b2s = (const float*)(smem + OFF_B2);
        #pragma unroll
        for (int mt = 0; mt < 2; ++mt)
            #pragma unroll
            for (int nt = 0; nt < 4; ++nt) {
                int row = wm * 32 + mt * 16 + (lid >> 2);
                int col = wn * 32 + nt * 8 + (lid & 3) * 2;
                float bc0 = b2s[col], bc1 = b2s[col + 1];
                int eA = e0 + row, eB = e0 + row + 8;
                if (eA < E)
                    *(float2*)&out[(size_t)eA * 64 + col] =
                        make_float2(acc[mt][nt][0] + bc0, acc[mt][nt][1] + bc1);
                if (eB < E)
                    *(float2*)&out[(size_t)eB * 64 + col] =
                        make_float2(acc[mt][nt][2] + bc0, acc[mt][nt][3] + bc1);
            }
    }
}

extern "C" void kernel_launch(void* const* d_in, const int* in_sizes, int n_in,
                              void* d_out, int out_size)
{
    const float* src = (const float*)d_in[0];
    const float* dst = (const float*)d_in[1];
    const float* ea  = (const float*)d_in[2];
    const float* W1  = (const float*)d_in[5];
    const float* b1  = (const float*)d_in[6];
    const float* W2  = (const float*)d_in[7];
    const float* b2  = (const float*)d_in[8];
    float* out = (float*)d_out;

    int E = in_sizes[0] / 64;

    cudaFuncSetAttribute(edge_mlp_mma,
                         cudaFuncAttributeMaxDynamicSharedMemorySize, SMEM_BYTES);

    int grid = (E + M_TILE - 1) / M_TILE;
    edge_mlp_mma<<<grid, THREADS, SMEM_BYTES>>>(src, dst, ea, W1, b1, W2, b2, out, E);
}

// round 5
// speedup vs baseline: 2.7405x; 1.0366x over previous
#include <cuda_runtime.h>
#include <cstdint>

#define THREADS 256
#define M_TILE  128

// ---------------- SMEM layout (bytes), MMA buffers 1024-aligned ----------------
#define OFF_B1   0
#define OFF_B2   256
#define OFF_XHI  1024
#define OFF_XLO  (OFF_XHI + 16384)     // 17408
#define OFF_W1HI (OFF_XLO + 16384)     // 33792
#define OFF_W1LO (OFF_W1HI + 24576)    // 58368
#define OFF_W2HI (OFF_W1LO + 24576)    // 82944
#define OFF_W2LO (OFF_W2HI + 8192)     // 91136
#define SMEM_BYTES (OFF_W2LO + 8192)   // 99328  -> 2 CTAs/SM

// ---------------- helpers ----------------
__device__ __forceinline__ uint32_t smem_u32(const void* p) {
    uint32_t a;
    asm("{ .reg .u64 t; cvta.to.shared.u64 t, %1; cvt.u32.u64 %0, t; }" : "=r"(a) : "l"(p));
    return a;
}
__device__ __forceinline__ uint32_t sw128(uint32_t o) { return o ^ ((o >> 3) & 0x70); }

__device__ __forceinline__ uint32_t pack2bf(float e0, float e1) {
    uint32_t r;
    asm("cvt.rn.bf16x2.f32 %0, %1, %2;" : "=r"(r) : "f"(e1), "f"(e0));
    return r;
}

// split 4 fp32 into bf16 hi/lo, 8B store each
__device__ __forceinline__ void split_store(char* hip, char* lop, float4 v) {
    uint32_t h01 = pack2bf(v.x, v.y);
    uint32_t h23 = pack2bf(v.z, v.w);
    float f0 = __uint_as_float(h01 << 16);
    float f1 = __uint_as_float(h01 & 0xFFFF0000u);
    float f2 = __uint_as_float(h23 << 16);
    float f3 = __uint_as_float(h23 & 0xFFFF0000u);
    uint32_t l01 = pack2bf(v.x - f0, v.y - f1);
    uint32_t l23 = pack2bf(v.z - f2, v.w - f3);
    *reinterpret_cast<uint2*>(hip) = make_uint2(h01, h23);
    *reinterpret_cast<uint2*>(lop) = make_uint2(l01, l23);
}

__device__ __forceinline__ void ldsm4(uint32_t r[4], uint32_t addr) {
    asm volatile("ldmatrix.sync.aligned.m8n8.x4.shared.b16 {%0,%1,%2,%3}, [%4];"
        : "=r"(r[0]), "=r"(r[1]), "=r"(r[2]), "=r"(r[3]) : "r"(addr));
}
__device__ __forceinline__ void ldsm4t(uint32_t r[4], uint32_t addr) {
    asm volatile("ldmatrix.sync.aligned.m8n8.x4.trans.shared.b16 {%0,%1,%2,%3}, [%4];"
        : "=r"(r[0]), "=r"(r[1]), "=r"(r[2]), "=r"(r[3]) : "r"(addr));
}
__device__ __forceinline__ void mma16816(float c[4], const uint32_t a[4], const uint32_t b[2]) {
    asm volatile(
        "mma.sync.aligned.m16n8k16.row.col.f32.bf16.bf16.f32 "
        "{%0,%1,%2,%3}, {%4,%5,%6,%7}, {%8,%9}, {%0,%1,%2,%3};"
        : "+f"(c[0]), "+f"(c[1]), "+f"(c[2]), "+f"(c[3])
        : "r"(a[0]), "r"(a[1]), "r"(a[2]), "r"(a[3]), "r"(b[0]), "r"(b[1]));
}
__device__ __forceinline__ uint32_t frag_addr(uint32_t base, int rbase, int cbase, int lane) {
    int row  = rbase + (lane & 15);
    int colb = cbase * 2 + (lane & 16);
    return base + sw128((uint32_t)(row * 128 + colb));
}
__device__ __forceinline__ void prefetch_l2(const void* p) {
    asm volatile("prefetch.global.L2 [%0];" :: "l"(p));
}

__global__ __launch_bounds__(THREADS, 2)
void edge_mlp_mma(const float* __restrict__ src, const float* __restrict__ dst,
                  const float* __restrict__ ea,
                  const float* __restrict__ W1, const float* __restrict__ b1,
                  const float* __restrict__ W2, const float* __restrict__ b2,
                  float* __restrict__ out, int E, int ntiles)
{
    extern __shared__ char smem[];
    const uint32_t sb = smem_u32(smem);
    const int tid = threadIdx.x;
    const int lid = tid & 31;
    const int wid = tid >> 5;

    const int wm = wid & 3;   // M group: rows 32*wm .. +31
    const int wn = wid >> 2;  // N group: cols 32*wn .. +31

    // ================= ONE-TIME: biases + weights =================
    if (tid < 64) {
        ((float*)(smem + OFF_B1))[tid] = b1[tid];
        ((float*)(smem + OFF_B2))[tid] = b2[tid];
    }
    #pragma unroll
    for (int i = 0; i < 12; ++i) {
        int idx = tid + i * THREADS;               // float4 index, 0..3071
        uint32_t off = sw128((uint32_t)((idx >> 4) * 128 + (idx & 15) * 8));
        float4 v = ((const float4*)W1)[idx];
        split_store(smem + OFF_W1HI + off, smem + OFF_W1LO + off, v);
    }
    #pragma unroll
    for (int i = 0; i < 4; ++i) {
        int idx = tid + i * THREADS;               // 0..1023
        uint32_t off = sw128((uint32_t)((idx >> 4) * 128 + (idx & 15) * 8));
        float4 v = ((const float4*)W2)[idx];
        split_store(smem + OFF_W2HI + off, smem + OFF_W2LO + off, v);
    }

    float acc[2][4][4];
    #pragma unroll
    for (int mt = 0; mt < 2; ++mt)
        #pragma unroll
        for (int nt = 0; nt < 4; ++nt)
            #pragma unroll
            for (int j = 0; j < 4; ++j) acc[mt][nt][j] = 0.f;

    // ---- X staging: GMEM -> split -> SMEM, plus L2 prefetch of the next segment ----
    auto stage_x = [&](const float* __restrict__ p, int e0, const float* __restrict__ pre) {
        #pragma unroll
        for (int i = 0; i < 8; ++i) {
            int idx = tid + i * THREADS;           // 0..2047
            int m = idx >> 4;
            int e = e0 + m;
            float4 v = (e < E) ? ((const float4*)p)[(size_t)e * 16 + (idx & 15)]
                               : make_float4(0.f, 0.f, 0.f, 0.f);
            uint32_t off = sw128((uint32_t)(m * 128 + (idx & 15) * 8));
            split_store(smem + OFF_XHI + off, smem + OFF_XLO + off, v);
        }
        if (pre) prefetch_l2((const char*)pre + (size_t)tid * 128);   // 32KB = 256 lines
    };

    // one 16-wide k-step: A from X hi/lo at col kk, B from weight buffers at row kg
    auto kstep = [&](int kk, uint32_t bhib, uint32_t blob, int kg) {
        uint32_t bhi[2][4], blo[2][4];
        ldsm4t(bhi[0], frag_addr(bhib, kg, wn * 32,      lid));
        ldsm4t(bhi[1], frag_addr(bhib, kg, wn * 32 + 16, lid));
        ldsm4t(blo[0], frag_addr(blob, kg, wn * 32,      lid));
        ldsm4t(blo[1], frag_addr(blob, kg, wn * 32 + 16, lid));
        #pragma unroll
        for (int mt = 0; mt < 2; ++mt) {
            uint32_t ahi[4], alo[4];
            ldsm4(ahi, frag_addr(sb + OFF_XHI, wm * 32 + mt * 16, kk, lid));
            ldsm4(alo, frag_addr(sb + OFF_XLO, wm * 32 + mt * 16, kk, lid));
            #pragma unroll
            for (int nt = 0; nt < 4; ++nt) {
                const uint32_t* bh = &bhi[nt >> 1][(nt & 1) * 2];
                const uint32_t* bl = &blo[nt >> 1][(nt & 1) * 2];
                mma16816(acc[mt][nt], ahi, bh);
                mma16816(acc[mt][nt], ahi, bl);
                mma16816(acc[mt][nt], alo, bh);
            }
        }
    };

    // ================= persistent tile loop =================
    for (int t = blockIdx.x; t < ntiles; t += gridDim.x) {
        const int e0 = t * M_TILE;
        const float* row0 = src + (size_t)e0 * 64;

        stage_x(src, e0, dst + (size_t)e0 * 64);
        __syncthreads();
        #pragma unroll
        for (int ks = 0; ks < 4; ++ks)
            kstep(ks * 16, sb + OFF_W1HI, sb + OFF_W1LO, ks * 16);
        __syncthreads();

        stage_x(dst, e0, ea + (size_t)e0 * 64);
        __syncthreads();
        #pragma unroll
        for (int ks = 0; ks < 4; ++ks)
            kstep(ks * 16, sb + OFF_W1HI, sb + OFF_W1LO, 64 + ks * 16);
        __syncthreads();

        {
            int tn = t + gridDim.x;
            const float* nxt = (tn < ntiles) ? src + (size_t)tn * M_TILE * 64 : row0;
            stage_x(ea, e0, nxt);
        }
        __syncthreads();
        #pragma unroll
        for (int ks = 0; ks < 4; ++ks)
            kstep(ks * 16, sb + OFF_W1HI, sb + OFF_W1LO, 128 + ks * 16);
        __syncthreads();                           // GEMM1 reads done; X free for H

        // ---- bias1 + ReLU + split -> H (reuse X hi/lo) ----
        {
            const float* b1s = (const float*)(smem + OFF_B1);
            #pragma unroll
            for (int mt = 0; mt < 2; ++mt)
                #pragma unroll
                for (int nt = 0; nt < 4; ++nt) {
                    int row = wm * 32 + mt * 16 + (lid >> 2);
                    int col = wn * 32 + nt * 8 + (lid & 3) * 2;
                    float bc0 = b1s[col], bc1 = b1s[col + 1];
                    float h0 = fmaxf(acc[mt][nt][0] + bc0, 0.f);
                    float h1 = fmaxf(acc[mt][nt][1] + bc1, 0.f);
                    float h2 = fmaxf(acc[mt][nt][2] + bc0, 0.f);
                    float h3 = fmaxf(acc[mt][nt][3] + bc1, 0.f);
                    uint32_t hA = pack2bf(h0, h1);
                    uint32_t hB = pack2bf(h2, h3);
                    uint32_t lA = pack2bf(h0 - __uint_as_float(hA << 16),
                                          h1 - __uint_as_float(hA & 0xFFFF0000u));
                    uint32_t lB = pack2bf(h2 - __uint_as_float(hB << 16),
                                          h3 - __uint_as_float(hB & 0xFFFF0000u));
                    uint32_t oA = sw128((uint32_t)(row * 128 + col * 2));
                    uint32_t oB = sw128((uint32_t)((row + 8) * 128 + col * 2));
                    *(uint32_t*)(smem + OFF_XHI + oA) = hA;
                    *(uint32_t*)(smem + OFF_XLO + oA) = lA;
                    *(uint32_t*)(smem + OFF_XHI + oB) = hB;
                    *(uint32_t*)(smem + OFF_XLO + oB) = lB;
                    acc[mt][nt][0] = acc[mt][nt][1] = acc[mt][nt][2] = acc[mt][nt][3] = 0.f;
                }
        }
        __syncthreads();

        // ================= GEMM2 (K = 64) =================
        #pragma unroll
        for (int ks = 0; ks < 4; ++ks)
            kstep(ks * 16, sb + OFF_W2HI, sb + OFF_W2LO, ks * 16);

        // ---- epilogue: + bias2, float2 stores; reset acc for next tile ----
        {
            const float* b2s = (const float*)(smem + OFF_B2);
            #pragma unroll
            for (int mt = 0; mt < 2; ++mt)
                #pragma unroll
                for (int nt = 0; nt < 4; ++nt) {
                    int row = wm * 32 + mt * 16 + (lid >> 2);
                    int col = wn * 32 + nt * 8 + (lid & 3) * 2;
                    float bc0 = b2s[col], bc1 = b2s[col + 1];
                    int eA = e0 + row, eB = e0 + row + 8;
                    if (eA < E)
                        *(float2*)&out[(size_t)eA * 64 + col] =
                            make_float2(acc[mt][nt][0] + bc0, acc[mt][nt][1] + bc1);
                    if (eB < E)
                        *(float2*)&out[(size_t)eB * 64 + col] =
                            make_float2(acc[mt][nt][2] + bc0, acc[mt][nt][3] + bc1);
                    acc[mt][nt][0] = acc[mt][nt][1] = acc[mt][nt][2] = acc[mt][nt][3] = 0.f;
                }
        }
        __syncthreads();                           // H reads done before next stage_x
    }
}

extern "C" void kernel_launch(void* const* d_in, const int* in_sizes, int n_in,
                              void* d_out, int out_size)
{
    const float* src = (const float*)d_in[0];
    const float* dst = (const float*)d_in[1];
    const float* ea  = (const float*)d_in[2];
    const float* W1  = (const float*)d_in[5];
    const float* b1  = (const float*)d_in[6];
    const float* W2  = (const float*)d_in[7];
    const float* b2  = (const float*)d_in[8];
    float* out = (float*)d_out;

    int E = in_sizes[0] / 64;
    int ntiles = (E + M_TILE - 1) / M_TILE;

    cudaFuncSetAttribute(edge_mlp_mma,
                         cudaFuncAttributeMaxDynamicSharedMemorySize, SMEM_BYTES);

    int grid = 2 * 148;
    if (grid > ntiles) grid = ntiles;
    edge_mlp_mma<<<grid, THREADS, SMEM_BYTES>>>(src, dst, ea, W1, b1, W2, b2, out, E, ntiles);
}